// round 2
// baseline (speedup 1.0000x reference)
#include <cuda_runtime.h>
#include <math.h>

#define NTOK 4096
#define DIM 1024
#define HID 2732
#define HID_PAD 2736
#define NEXP 8
#define MAXM 4096

// Scratch (static __device__ per allocation rules): H buffer [E*MAXM rows][HID_PAD]
__device__ float g_H[(size_t)NEXP * MAXM * HID_PAD];
__device__ int   g_cnt[NEXP];
__device__ int   g_tok[NEXP * MAXM];
__device__ float g_w[NEXP * MAXM];

// ---------------------------------------------------------------------------
__global__ void zero_kernel(float* __restrict__ out) {
    int i = blockIdx.x * blockDim.x + threadIdx.x;
    if (i < NTOK * DIM) out[i] = 0.f;
    if (i < NEXP) g_cnt[i] = 0;
}

// ---------------------------------------------------------------------------
// One warp per token: scores = x . Wg[e], top-2, softmax, route.
__global__ void gate_kernel(const float* __restrict__ x,
                            const float* __restrict__ Wg) {
    int gtid = blockIdx.x * blockDim.x + threadIdx.x;
    int tok  = gtid >> 5;
    int lane = gtid & 31;
    if (tok >= NTOK) return;
    const float* xr = x + (size_t)tok * DIM;
    float s[NEXP];
#pragma unroll
    for (int e = 0; e < NEXP; e++) s[e] = 0.f;
    for (int k = lane; k < DIM; k += 32) {
        float xv = xr[k];
#pragma unroll
        for (int e = 0; e < NEXP; e++) s[e] += xv * Wg[e * DIM + k];
    }
#pragma unroll
    for (int e = 0; e < NEXP; e++) {
#pragma unroll
        for (int off = 16; off; off >>= 1)
            s[e] += __shfl_xor_sync(0xffffffffu, s[e], off);
    }
    if (lane == 0) {
        int e0 = 0;
#pragma unroll
        for (int e = 1; e < NEXP; e++) if (s[e] > s[e0]) e0 = e;
        int e1 = (e0 == 0) ? 1 : 0;
#pragma unroll
        for (int e = 0; e < NEXP; e++) if (e != e0 && s[e] > s[e1]) e1 = e;
        float p1 = __expf(s[e1] - s[e0]);
        float w0 = 1.f / (1.f + p1);
        float w1 = p1 * w0;
        int q0 = atomicAdd(&g_cnt[e0], 1);
        g_tok[e0 * MAXM + q0] = tok;  g_w[e0 * MAXM + q0] = w0;
        int q1 = atomicAdd(&g_cnt[e1], 1);
        g_tok[e1 * MAXM + q1] = tok;  g_w[e1 * MAXM + q1] = w1;
    }
}

// ---------------------------------------------------------------------------
// Tiled SGEMM over gathered rows. BM=BN=128, BK=8, 256 threads, 8x8/thread.
// MODE 0: H1 = Xg @ W1^T              (store to g_H)
// MODE 1: H  = silu(H1) * (Xg @ W3^T) (read g_H, combine, store; zero pads)
// MODE 2: out[token] += w * (H @ W2^T) (atomicAdd)
template <int MODE>
__global__ void __launch_bounds__(256, 2)
gemm_kernel(const float* __restrict__ Xg,
            const float* __restrict__ Wbase,
            float* __restrict__ out) {
    const int e   = blockIdx.z;
    const int cnt = g_cnt[e];
    const int m0  = blockIdx.y * 128;
    if (m0 >= cnt) return;
    const int n0  = blockIdx.x * 128;

    const int K       = (MODE == 2) ? HID_PAD : DIM;  // A pads are zeroed
    const int NB      = (MODE == 2) ? DIM : HID;      // B row count
    const int bstride = (MODE == 2) ? HID : DIM;      // B row stride
    const float* W = Wbase + (size_t)e * (size_t)NB * (size_t)bstride;

    __shared__ float As[8][128];
    __shared__ float Bs[8][128];

    const int tid  = threadIdx.x;
    const int arow = tid >> 1;           // 0..127
    const int ak   = (tid & 1) * 4;      // 0 or 4

    const bool a_valid = (m0 + arow) < cnt;
    const float* Arow = nullptr;
    if (a_valid) {
        if (MODE == 2)
            Arow = g_H + (size_t)(e * MAXM + m0 + arow) * HID_PAD;
        else
            Arow = Xg + (size_t)g_tok[e * MAXM + m0 + arow] * DIM;
    }
    const bool b_valid = (n0 + arow) < NB;
    const float* Brow = b_valid ? (W + (size_t)(n0 + arow) * bstride) : nullptr;

    const int tx = tid & 15;             // column group
    const int ty = tid >> 4;             // row group

    float acc[8][8];
#pragma unroll
    for (int i = 0; i < 8; i++)
#pragma unroll
        for (int j = 0; j < 8; j++) acc[i][j] = 0.f;

    for (int k0 = 0; k0 < K; k0 += 8) {
        float4 av = make_float4(0.f, 0.f, 0.f, 0.f);
        float4 bv = make_float4(0.f, 0.f, 0.f, 0.f);
        if (a_valid) av = *(const float4*)(Arow + k0 + ak);
        if (b_valid && (MODE != 2 || (k0 + ak) < HID))
            bv = *(const float4*)(Brow + k0 + ak);
        __syncthreads();
        As[ak + 0][arow] = av.x; As[ak + 1][arow] = av.y;
        As[ak + 2][arow] = av.z; As[ak + 3][arow] = av.w;
        Bs[ak + 0][arow] = bv.x; Bs[ak + 1][arow] = bv.y;
        Bs[ak + 2][arow] = bv.z; Bs[ak + 3][arow] = bv.w;
        __syncthreads();
#pragma unroll
        for (int kk = 0; kk < 8; kk++) {
            float a_frag[8], b_frag[8];
            *(float4*)(a_frag)     = *(const float4*)&As[kk][ty * 8];
            *(float4*)(a_frag + 4) = *(const float4*)&As[kk][ty * 8 + 4];
            *(float4*)(b_frag)     = *(const float4*)&Bs[kk][tx * 8];
            *(float4*)(b_frag + 4) = *(const float4*)&Bs[kk][tx * 8 + 4];
#pragma unroll
            for (int i = 0; i < 8; i++)
#pragma unroll
                for (int j = 0; j < 8; j++)
                    acc[i][j] += a_frag[i] * b_frag[j];
        }
    }

    // Epilogue
#pragma unroll
    for (int i = 0; i < 8; i++) {
        int row = m0 + ty * 8 + i;
        if (row >= cnt) continue;
        if (MODE == 0) {
            size_t base = (size_t)(e * MAXM + row) * HID_PAD;
#pragma unroll
            for (int j = 0; j < 8; j++) {
                int n = n0 + tx * 8 + j;
                if (n < HID) g_H[base + n] = acc[i][j];
            }
        } else if (MODE == 1) {
            size_t base = (size_t)(e * MAXM + row) * HID_PAD;
#pragma unroll
            for (int j = 0; j < 8; j++) {
                int n = n0 + tx * 8 + j;
                if (n < HID) {
                    float h1  = g_H[base + n];
                    float sig = 1.f / (1.f + __expf(-h1));
                    g_H[base + n] = h1 * sig * acc[i][j];
                } else if (n < HID_PAD) {
                    g_H[base + n] = 0.f;   // zero pads for pass-B K loop
                }
            }
        } else {
            int slot  = e * MAXM + row;
            float wv  = g_w[slot];
            int token = g_tok[slot];
            size_t base = (size_t)token * DIM + n0 + tx * 8;
#pragma unroll
            for (int j = 0; j < 8; j++)
                atomicAdd(&out[base + j], wv * acc[i][j]);
        }
    }
}

// ---------------------------------------------------------------------------
extern "C" void kernel_launch(void* const* d_in, const int* in_sizes, int n_in,
                              void* d_out, int out_size) {
    const float* x  = (const float*)d_in[0];
    const float* Wg = (const float*)d_in[1];
    const float* W1 = (const float*)d_in[2];
    const float* W2 = (const float*)d_in[3];
    const float* W3 = (const float*)d_in[4];
    float* out = (float*)d_out;

    zero_kernel<<<(NTOK * DIM + 1023) / 1024, 1024>>>(out);
    gate_kernel<<<(NTOK * 32 + 255) / 256, 256>>>(x, Wg);

    dim3 gA((HID + 127) / 128, MAXM / 128, NEXP);   // 22 x 32 x 8
    gemm_kernel<0><<<gA, 256>>>(x, W1, nullptr);
    gemm_kernel<1><<<gA, 256>>>(x, W3, nullptr);

    dim3 gB(DIM / 128, MAXM / 128, NEXP);           // 8 x 32 x 8
    gemm_kernel<2><<<gB, 256>>>(nullptr, W2, out);
}